// round 16
// baseline (speedup 1.0000x reference)
#include <cuda_runtime.h>
#include <cuda_fp16.h>
#include <cstdint>
#include <cstddef>

#define B_  8
#define N_  2048
#define KD  256
#define VD  256
#define AD  128
#define NEG_INF (-3.402823466e38f)

typedef unsigned char u8;
typedef unsigned int  u32;

// ------------------- device scratch -------------------
__device__ __align__(16) u8 g_k1pack[(size_t)B_ * 16 * 2 * 32768];   // 8 MB
__device__ __align__(16) u8 g_k2pack[(size_t)B_ * 16 * 2 * 32768];   // 8 MB
__device__ __align__(16) u8 g_v1pack[(size_t)B_ * 32 * 32768];       // 8 MB
__device__ __align__(16) u8 g_v2pack[(size_t)B_ * 32 * 32768];       // 8 MB
__device__ float g_S[(size_t)B_ * N_ * N_];                          // 128 MB
__device__ __align__(16) u8 g_A2[(size_t)B_ * 16 * 32 * 16384];      // 64 MB
__device__ __align__(16) u8 g_A1[(size_t)B_ * 16 * 32 * 16384];      // 64 MB
__device__ float g_rmpart[(size_t)B_ * N_ * 64];
__device__ float g_cmpart[(size_t)B_ * N_ * 32];
__device__ float g_rspart[(size_t)B_ * N_ * 64];   // exppack writes even pair-slots; odd stay 0
__device__ float g_cspart[(size_t)B_ * N_ * 64];   // exppack writes even pair-slots; odd stay 0
__device__ float g_rowmax[B_ * N_];
__device__ float g_colmax[B_ * N_];
__device__ float g_rsinv[B_ * N_];
__device__ float g_csinv[B_ * N_];

// ------------------- helpers -------------------
__device__ __forceinline__ u32 smem_u32(const void* p) {
    u32 a;
    asm("{ .reg .u64 t; cvta.to.shared.u64 t, %1; cvt.u32.u64 %0, t; }" : "=r"(a) : "l"(p));
    return a;
}
__device__ __forceinline__ u32 f16x2_pack(float a, float b) {
    u32 r;
    asm("cvt.rn.f16x2.f32 %0, %1, %2;" : "=r"(r) : "f"(b), "f"(a));
    return r;
}
__device__ __forceinline__ void split2(float f0, float f1, u32& hi, u32& lo) {
    u32 h;
    asm("cvt.rn.bf16x2.f32 %0, %1, %2;" : "=r"(h) : "f"(f1), "f"(f0));
    float h0 = __uint_as_float(h << 16);
    float h1 = __uint_as_float(h & 0xFFFF0000u);
    u32 l;
    asm("cvt.rn.bf16x2.f32 %0, %1, %2;" : "=r"(l) : "f"(f1 - h1), "f"(f0 - h0));
    hi = h; lo = l;
}
__device__ __forceinline__ void mma_bf16(float* c, const u32* a, u32 b0, u32 b1) {
    asm volatile(
        "mma.sync.aligned.m16n8k16.row.col.f32.bf16.bf16.f32 "
        "{%0,%1,%2,%3}, {%4,%5,%6,%7}, {%8,%9}, {%0,%1,%2,%3};"
        : "+f"(c[0]), "+f"(c[1]), "+f"(c[2]), "+f"(c[3])
        : "r"(a[0]), "r"(a[1]), "r"(a[2]), "r"(a[3]), "r"(b0), "r"(b1));
}
__device__ __forceinline__ void mma_f16(float* c, const u32* a, u32 b0, u32 b1) {
    asm volatile(
        "mma.sync.aligned.m16n8k16.row.col.f32.f16.f16.f32 "
        "{%0,%1,%2,%3}, {%4,%5,%6,%7}, {%8,%9}, {%0,%1,%2,%3};"
        : "+f"(c[0]), "+f"(c[1]), "+f"(c[2]), "+f"(c[3])
        : "r"(a[0]), "r"(a[1]), "r"(a[2]), "r"(a[3]), "r"(b0), "r"(b1));
}
__device__ __forceinline__ void ldsm4(u32* r, u32 addr) {
    asm volatile("ldmatrix.sync.aligned.m8n8.x4.shared.b16 {%0,%1,%2,%3}, [%4];"
                 : "=r"(r[0]), "=r"(r[1]), "=r"(r[2]), "=r"(r[3]) : "r"(addr));
}
#define CP_ASYNC16(dst, src)                                                \
    asm volatile("cp.async.cg.shared.global [%0], [%1], 16;"                \
                 :: "r"(dst), "l"(__cvta_generic_to_global(src)))
#define CP_COMMIT()  asm volatile("cp.async.commit_group;")
#define CP_WAITG(n)  asm volatile("cp.async.wait_group %0;" :: "n"(n))

// ============================================================
// proj (unchanged)
// ============================================================
#define P_SMEM 99840
__global__ __launch_bounds__(256) void proj_kernel(const float* __restrict__ k1,
                                                   const float* __restrict__ W1,
                                                   const float* __restrict__ b1v,
                                                   const float* __restrict__ k2,
                                                   const float* __restrict__ W2,
                                                   const float* __restrict__ b2v) {
    extern __shared__ u8 sm[];
    const u32 sb = smem_u32(sm);
    float* Wst = (float*)(sm + 65536);
    float* bc  = (float*)(sm + 99328);
    const int which = blockIdx.y;
    const float* A = which ? k2 : k1;
    const float* W = which ? W2 : W1;
    const float* bias = which ? b2v : b1v;
    const int t = threadIdx.x, lane = t & 31, wid = t >> 5;
    const int wm = wid & 1, wn = wid >> 1;
    const int m0 = blockIdx.x * 128;
    if (t < 128) bc[t] = bias[t];

    float acc[4][4][4];
#pragma unroll
    for (int i = 0; i < 4; i++)
#pragma unroll
        for (int j = 0; j < 4; j++)
#pragma unroll
            for (int q = 0; q < 4; q++) acc[i][j][q] = 0.f;

    const int lr = lane & 15;
    for (int kc = 0; kc < 4; kc++) {
        __syncthreads();
        {
            const int m = t >> 1, kh = (t & 1) * 32;
            const float* Ar = A + (size_t)(m0 + m) * KD + kc * 64 + kh;
            const u32 xv = (u32)((m & 7) * 16);
#pragma unroll
            for (int j = 0; j < 8; j++) {
                float4 f = *(const float4*)(Ar + 4 * j);
                u32 h01, l01, h23, l23;
                split2(f.x, f.y, h01, l01); split2(f.z, f.w, h23, l23);
                const u32 off = (u32)(m * 128) + (((u32)((kh + 4 * j) * 2)) ^ xv);
                *(uint2*)(sm + off)         = make_uint2(h01, h23);
                *(uint2*)(sm + 16384 + off) = make_uint2(l01, l23);
            }
        }
        {
            const int k = t >> 2, ns = (t & 3) * 32;
            const float* Wr = W + (size_t)(kc * 64 + k) * AD + ns;
#pragma unroll
            for (int j = 0; j < 8; j++)
                *(float4*)&Wst[k * 132 + ns + 4 * j] = *(const float4*)(Wr + 4 * j);
        }
        __syncthreads();
        {
            const int n = t >> 1, kh = (t & 1) * 32;
            const u32 xv = (u32)((n & 7) * 16);
#pragma unroll
            for (int jq = 0; jq < 8; jq++) {
                float w0 = Wst[(kh + 4 * jq + 0) * 132 + n];
                float w1 = Wst[(kh + 4 * jq + 1) * 132 + n];
                float w2 = Wst[(kh + 4 * jq + 2) * 132 + n];
                float w3 = Wst[(kh + 4 * jq + 3) * 132 + n];
                u32 h01, l01, h23, l23;
                split2(w0, w1, h01, l01); split2(w2, w3, h23, l23);
                const u32 off = (u32)(n * 128) + (((u32)((kh + 4 * jq) * 2)) ^ xv);
                *(uint2*)(sm + 32768 + off) = make_uint2(h01, h23);
                *(uint2*)(sm + 49152 + off) = make_uint2(l01, l23);
            }
        }
        __syncthreads();
#pragma unroll
        for (int ks = 0; ks < 4; ks++) {
            const u32 kb = (u32)((ks * 16 + (lane >> 4) * 8) * 2);
            u32 ah[4][4], al[4][4], bh[2][4], bl[2][4];
#pragma unroll
            for (int mf = 0; mf < 4; mf++) {
                const int r = wm * 64 + mf * 16 + lr;
                const u32 ro = (u32)(r * 128) + (kb ^ ((u32)((r & 7) * 16)));
                ldsm4(ah[mf], sb + ro);
                ldsm4(al[mf], sb + 16384 + ro);
            }
#pragma unroll
            for (int nb = 0; nb < 2; nb++) {
                const int r = wn * 32 + nb * 16 + lr;
                const u32 ro = (u32)(r * 128) + (kb ^ ((u32)((r & 7) * 16)));
                ldsm4(bh[nb], sb + 32768 + ro);
                ldsm4(bl[nb], sb + 49152 + ro);
            }
#pragma unroll
            for (int mf = 0; mf < 4; mf++)
#pragma unroll
                for (int n8 = 0; n8 < 4; n8++) {
                    const int nb = n8 >> 1, i = n8 & 1;
                    mma_bf16(acc[mf][n8], ah[mf], bh[nb][i], bh[nb][i + 2]);
                    mma_bf16(acc[mf][n8], al[mf], bh[nb][i], bh[nb][i + 2]);
                    mma_bf16(acc[mf][n8], ah[mf], bl[nb][i], bl[nb][i + 2]);
                }
        }
    }
    __syncthreads();
    float* smT = (float*)sm;
    const int g = lane >> 2, tig = lane & 3;
#pragma unroll
    for (int mf = 0; mf < 4; mf++)
#pragma unroll
        for (int n8 = 0; n8 < 4; n8++) {
            const int r = wm * 64 + mf * 16 + g;
            const int c = wn * 32 + n8 * 8 + tig * 2;
            const float b0 = bc[c], b1 = bc[c + 1];
            *(float2*)&smT[r * 132 + c]       = make_float2(acc[mf][n8][0] + b0, acc[mf][n8][1] + b1);
            *(float2*)&smT[(r + 8) * 132 + c] = make_float2(acc[mf][n8][2] + b0, acc[mf][n8][3] + b1);
        }
    __syncthreads();
    {
        const int b_ = m0 / N_, mt = (m0 % N_) / 128;
        u8* hibase = (which ? g_k2pack : g_k1pack) + ((size_t)(b_ * 16 + mt) * 2) * 32768;
        u8* lobase = hibase + 32768;
        const int row = t >> 1, ch = t & 1;
        const u32 xv = (u32)((row & 7) * 16);
#pragma unroll
        for (int j = 0; j < 16; j++) {
            float f0 = smT[row * 132 + ch * 64 + 4 * j + 0];
            float f1 = smT[row * 132 + ch * 64 + 4 * j + 1];
            float f2 = smT[row * 132 + ch * 64 + 4 * j + 2];
            float f3 = smT[row * 132 + ch * 64 + 4 * j + 3];
            u32 h01, l01, h23, l23;
            split2(f0, f1, h01, l01); split2(f2, f3, h23, l23);
            const u32 off = (u32)(ch * 16384 + row * 128) + (((u32)(8 * j)) ^ xv);
            *(uint2*)(hibase + off) = make_uint2(h01, h23);
            *(uint2*)(lobase + off) = make_uint2(l01, l23);
        }
    }
}

// ============================================================
// vpack (unchanged)
// ============================================================
__global__ __launch_bounds__(256) void vpack_kernel(const float* __restrict__ v1,
                                                    const float* __restrict__ v2) {
    __shared__ float sv[64][68];
    const int which = blockIdx.z;
    const float* v = which ? v2 : v1;
    u8* dst = which ? g_v2pack : g_v1pack;
    const int b = blockIdx.y, kc = blockIdx.x;
    const int t = threadIdx.x;
    u8* tile = dst + ((size_t)b * 32 + kc) * 32768;
    for (int dc = 0; dc < 4; dc++) {
#pragma unroll
        for (int i = 0; i < 4; i++) {
            const int q = t + i * 256;
            const int kr = q >> 4, dl = (q & 15) * 4;
            float4 f = *(const float4*)(v + ((size_t)b * N_ + kc * 64 + kr) * VD + dc * 64 + dl);
            sv[dl + 0][kr] = f.x; sv[dl + 1][kr] = f.y;
            sv[dl + 2][kr] = f.z; sv[dl + 3][kr] = f.w;
        }
        __syncthreads();
        const int dl = t >> 2, q = t & 3;
        const int row = dc * 64 + dl;
        const u32 xv = (u32)((row & 7) * 16);
#pragma unroll
        for (int j = 0; j < 4; j++) {
            const int k0 = q * 16 + j * 4;
            u32 p01 = f16x2_pack(sv[dl][k0 + 0], sv[dl][k0 + 1]);
            u32 p23 = f16x2_pack(sv[dl][k0 + 2], sv[dl][k0 + 3]);
            *(uint2*)(tile + row * 128 + (((u32)(k0 * 2)) ^ xv)) = make_uint2(p01, p23);
        }
        __syncthreads();
    }
}

// ============================================================
// score (unchanged)
// ============================================================
#define SC_SMEM 65536
__global__ __launch_bounds__(256) void score_kernel() {
    extern __shared__ u8 sm[];
    const u32 sb = smem_u32(sm);
    const int t = threadIdx.x, lane = t & 31, wid = t >> 5;
    const int wm = wid & 1, wn = wid >> 1;
    const int b = blockIdx.z, mt = blockIdx.y, nt = blockIdx.x;

    const u8* a_hi = g_k1pack + ((size_t)(b * 16 + mt) * 2) * 32768;
    const u8* a_lo = a_hi + 32768;
    const u8* b_hi = g_k2pack + ((size_t)(b * 16 + nt) * 2) * 32768;
    const u8* b_lo = b_hi + 32768;

    float acc[4][4][4];
#pragma unroll
    for (int i = 0; i < 4; i++)
#pragma unroll
        for (int j = 0; j < 4; j++)
#pragma unroll
            for (int q = 0; q < 4; q++) acc[i][j][q] = 0.f;

    const int lr = lane & 15;
    for (int kc = 0; kc < 2; kc++) {
        __syncthreads();
        const u32 off0 = (u32)(kc * 16384);
#pragma unroll
        for (int j = 0; j < 4; j++) {
            const u32 o = (u32)((j * 256 + t) * 16);
            CP_ASYNC16(sb + o,         a_hi + off0 + o);
            CP_ASYNC16(sb + 16384 + o, a_lo + off0 + o);
            CP_ASYNC16(sb + 32768 + o, b_hi + off0 + o);
            CP_ASYNC16(sb + 49152 + o, b_lo + off0 + o);
        }
        CP_COMMIT(); CP_WAITG(0);
        __syncthreads();
#pragma unroll
        for (int ks = 0; ks < 4; ks++) {
            const u32 kb = (u32)((ks * 16 + (lane >> 4) * 8) * 2);
            u32 ah[4][4], al[4][4], bh[2][4], bl[2][4];
#pragma unroll
            for (int mf = 0; mf < 4; mf++) {
                const int r = wm * 64 + mf * 16 + lr;
                const u32 ro = (u32)(r * 128) + (kb ^ ((u32)((r & 7) * 16)));
                ldsm4(ah[mf], sb + ro);
                ldsm4(al[mf], sb + 16384 + ro);
            }
#pragma unroll
            for (int nb = 0; nb < 2; nb++) {
                const int r = wn * 32 + nb * 16 + lr;
                const u32 ro = (u32)(r * 128) + (kb ^ ((u32)((r & 7) * 16)));
                ldsm4(bh[nb], sb + 32768 + ro);
                ldsm4(bl[nb], sb + 49152 + ro);
            }
#pragma unroll
            for (int mf = 0; mf < 4; mf++)
#pragma unroll
                for (int n8 = 0; n8 < 4; n8++) {
                    const int nb = n8 >> 1, i = n8 & 1;
                    mma_bf16(acc[mf][n8], ah[mf], bh[nb][i], bh[nb][i + 2]);
                    mma_bf16(acc[mf][n8], al[mf], bh[nb][i], bh[nb][i + 2]);
                    mma_bf16(acc[mf][n8], ah[mf], bl[nb][i], bl[nb][i + 2]);
                }
        }
    }

    const int g = lane >> 2, tig = lane & 3;
    float rowm[8], colm[8];
#pragma unroll
    for (int i = 0; i < 8; i++) { rowm[i] = NEG_INF; colm[i] = NEG_INF; }
    float* Sp = g_S + ((size_t)(b * N_ + mt * 128)) * N_ + nt * 128;
#pragma unroll
    for (int mf = 0; mf < 4; mf++) {
        const int r0 = wm * 64 + mf * 16 + g;
#pragma unroll
        for (int n8 = 0; n8 < 4; n8++) {
            const int c = wn * 32 + n8 * 8 + tig * 2;
            const float v0 = acc[mf][n8][0], v1 = acc[mf][n8][1];
            const float v2 = acc[mf][n8][2], v3 = acc[mf][n8][3];
            *(float2*)(Sp + (size_t)r0 * N_ + c)       = make_float2(v0, v1);
            *(float2*)(Sp + (size_t)(r0 + 8) * N_ + c) = make_float2(v2, v3);
            rowm[mf * 2 + 0] = fmaxf(rowm[mf * 2 + 0], fmaxf(v0, v1));
            rowm[mf * 2 + 1] = fmaxf(rowm[mf * 2 + 1], fmaxf(v2, v3));
            colm[n8 * 2 + 0] = fmaxf(colm[n8 * 2 + 0], fmaxf(v0, v2));
            colm[n8 * 2 + 1] = fmaxf(colm[n8 * 2 + 1], fmaxf(v1, v3));
        }
    }
#pragma unroll
    for (int i = 0; i < 8; i++) {
        rowm[i] = fmaxf(rowm[i], __shfl_xor_sync(0xffffffffu, rowm[i], 1));
        rowm[i] = fmaxf(rowm[i], __shfl_xor_sync(0xffffffffu, rowm[i], 2));
        colm[i] = fmaxf(colm[i], __shfl_xor_sync(0xffffffffu, colm[i], 4));
        colm[i] = fmaxf(colm[i], __shfl_xor_sync(0xffffffffu, colm[i], 8));
        colm[i] = fmaxf(colm[i], __shfl_xor_sync(0xffffffffu, colm[i], 16));
    }
    if (tig == 0) {
#pragma unroll
        for (int mf = 0; mf < 4; mf++)
#pragma unroll
            for (int rh = 0; rh < 2; rh++) {
                const int row = mt * 128 + wm * 64 + mf * 16 + rh * 8 + g;
                g_rmpart[((size_t)(b * N_ + row)) * 64 + nt * 4 + wn] = rowm[mf * 2 + rh];
            }
    }
    if (g == 0) {
#pragma unroll
        for (int n8 = 0; n8 < 4; n8++)
#pragma unroll
            for (int cp = 0; cp < 2; cp++) {
                const int col = nt * 128 + wn * 32 + n8 * 8 + tig * 2 + cp;
                g_cmpart[((size_t)(b * N_ + col)) * 32 + mt * 2 + wm] = colm[n8 * 2 + cp];
            }
    }
}

// ============================================================
// maxreduce (unchanged)
// ============================================================
__global__ void maxreduce_kernel() {
    const int which = blockIdx.y;
    const int t = threadIdx.x;
    const int item = blockIdx.x * 32 + (t >> 3);
    const int j = t & 7;
    float m;
    if (which == 0) {
        const float* p = g_rmpart + (size_t)item * 64 + j * 8;
        float4 a = *(const float4*)p, b4 = *(const float4*)(p + 4);
        m = fmaxf(fmaxf(fmaxf(a.x, a.y), fmaxf(a.z, a.w)),
                  fmaxf(fmaxf(b4.x, b4.y), fmaxf(b4.z, b4.w)));
    } else {
        const float* p = g_cmpart + (size_t)item * 32 + j * 4;
        float4 a = *(const float4*)p;
        m = fmaxf(fmaxf(a.x, a.y), fmaxf(a.z, a.w));
    }
    m = fmaxf(m, __shfl_xor_sync(0xffffffffu, m, 1));
    m = fmaxf(m, __shfl_xor_sync(0xffffffffu, m, 2));
    m = fmaxf(m, __shfl_xor_sync(0xffffffffu, m, 4));
    if (j == 0) (which ? g_colmax : g_rowmax)[item] = m;
}

// ============================================================
// exppack FUSED v2 (unchanged R15)
// ============================================================
#define EF_SMEM 20608
__global__ __launch_bounds__(256) void exppack_kernel() {
    extern __shared__ u8 sm[];
    const int t = threadIdx.x;
    const int nt = blockIdx.x, mt = blockIdx.y;
    const int b = blockIdx.z >> 1, half = blockIdx.z & 1;

    // Phase A: register-direct
    {
        const int ch = t & 7, rg = t >> 3;
        u8* tile = g_A2 + (((size_t)(b * 16 + mt) * 32) + nt * 2 + half) * 16384;
#pragma unroll
        for (int i = 0; i < 4; i++) {
            const int r = rg + i * 32;
            const float* Sp = g_S + ((size_t)(b * N_ + mt * 128 + r)) * N_
                              + nt * 128 + half * 64 + ch * 8;
            const float rm = g_rowmax[b * N_ + mt * 128 + r];
            float4 f0 = *(const float4*)Sp;
            float4 f1 = *(const float4*)(Sp + 4);
            float e0 = __expf(f0.x - rm), e1 = __expf(f0.y - rm);
            float e2 = __expf(f0.z - rm), e3 = __expf(f0.w - rm);
            float e4 = __expf(f1.x - rm), e5 = __expf(f1.y - rm);
            float e6 = __expf(f1.z - rm), e7 = __expf(f1.w - rm);
            float rs = ((e0 + e1) + (e2 + e3)) + ((e4 + e5) + (e6 + e7));
            uint4 v = make_uint4(f16x2_pack(e0, e1), f16x2_pack(e2, e3),
                                 f16x2_pack(e4, e5), f16x2_pack(e6, e7));
            const u32 off = (u32)(r * 128) + (((u32)(ch * 16)) ^ ((u32)((r & 7) * 16)));
            *(uint4*)(tile + off) = v;
            rs += __shfl_xor_sync(0xffffffffu, rs, 1);
            rs += __shfl_xor_sync(0xffffffffu, rs, 2);
            rs += __shfl_xor_sync(0xffffffffu, rs, 4);
            if (ch == 0)
                g_rspart[((size_t)(b * N_ + mt * 128 + r)) * 64 + nt * 4 + half * 2] = rs;
        }
    }

    // Phase T: staged
    {
        float* csbuf = (float*)(sm + 16384);
        const int lane5 = t & 31, kseg = t >> 5;
        const int colq = lane5 * 4;
        const int k0 = mt * 128 + half * 64 + kseg * 8;
        const float* Sp = g_S + ((size_t)(b * N_) + k0) * N_ + nt * 128 + colq;
        const float4 cm4 = *(const float4*)(g_colmax + b * N_ + nt * 128 + colq);

        float e[8][4];
        float cs[4] = {0.f, 0.f, 0.f, 0.f};
#pragma unroll
        for (int k = 0; k < 8; k++) {
            float4 f = *(const float4*)(Sp + (size_t)k * N_);
            e[k][0] = __expf(f.x - cm4.x); e[k][1] = __expf(f.y - cm4.y);
            e[k][2] = __expf(f.z - cm4.z); e[k][3] = __expf(f.w - cm4.w);
            cs[0] += e[k][0]; cs[1] += e[k][1]; cs[2] += e[k][2]; cs[3] += e[k][3];
        }
#pragma unroll
        for (int j = 0; j < 4; j++) {
            const int c = (j + (lane5 >> 1)) & 3;
            const int row = colq + c;
            uint4 v = make_uint4(f16x2_pack(e[0][c], e[1][c]), f16x2_pack(e[2][c], e[3][c]),
                                 f16x2_pack(e[4][c], e[5][c]), f16x2_pack(e[6][c], e[7][c]));
            const u32 off = (u32)(row * 128) + (((u32)(kseg * 16)) ^ ((u32)((row & 7) * 16)));
            *(uint4*)(sm + off) = v;
        }
#pragma unroll
        for (int c = 0; c < 4; c++) csbuf[kseg * 132 + colq + c] = cs[c];
        __syncthreads();
        if (t < 128) {
            float s = 0.f;
#pragma unroll
            for (int ks2 = 0; ks2 < 8; ks2++) s += csbuf[ks2 * 132 + t];
            g_cspart[((size_t)(b * N_ + nt * 128 + t)) * 64 + mt * 4 + half * 2] = s;
        }
        u8* dst = g_A1 + (((size_t)(b * 16 + nt) * 32) + mt * 2 + half) * 16384;
#pragma unroll
        for (int i = 0; i < 4; i++) {
            const int q = (t & 7) + ((t >> 3) + i * 32) * 8;
            *(uint4*)(dst + q * 16) = *(const uint4*)(sm + q * 16);
        }
    }
}

// ============================================================
// sumreduce (unchanged)
// ============================================================
__global__ void sumreduce_kernel() {
    const int which = blockIdx.y;
    const int t = threadIdx.x;
    const int item = blockIdx.x * 32 + (t >> 3);
    const int j = t & 7;
    const float* p = (which ? g_cspart : g_rspart) + (size_t)item * 64 + j * 8;
    float4 a = *(const float4*)p, b4 = *(const float4*)(p + 4);
    float s = (a.x + a.y) + (a.z + a.w) + (b4.x + b4.y) + (b4.z + b4.w);
    s += __shfl_xor_sync(0xffffffffu, s, 1);
    s += __shfl_xor_sync(0xffffffffu, s, 2);
    s += __shfl_xor_sync(0xffffffffu, s, 4);
    if (j == 0) (which ? g_csinv : g_rsinv)[item] = 1.f / s;
}

// ============================================================
// o v2: chunk-PAIR pipeline (K-step 128): 16 iterations, 128 mma per barrier.
// Buffers: A 3x32K @0 | V 3x32K @98304 (192KB, 1 CTA/SM, 8 warps).
// A pair is contiguous (2 x 16K kc tiles); V pair = two 16K ntv-half chunks.
// ============================================================
#define O_SMEM 196608
__global__ __launch_bounds__(256, 1) void o_kernel(float* __restrict__ o2_out,
                                                   float* __restrict__ o1_out) {
    extern __shared__ u8 sm[];
    const u32 sb = smem_u32(sm);
    const int t = threadIdx.x, lane = t & 31, wid = t >> 5;
    const int wm = wid & 1, wn = wid >> 1;
    const int which = blockIdx.z, b = blockIdx.y;
    const int mt = blockIdx.x >> 1, ntv = blockIdx.x & 1;

    const u8* Abase = (which ? g_A1 : g_A2) + ((size_t)(b * 16 + mt) * 32) * 16384;
    const u8* Vbase = (which ? g_v1pack : g_v2pack) + ((size_t)b * 32) * 32768 + (size_t)ntv * 16384;
    const float* inv = (which ? g_csinv : g_rsinv) + b * N_ + mt * 128;
    float* outp = which ? o1_out : o2_out;

    float acc[4][4][4];
#pragma unroll
    for (int i = 0; i < 4; i++)
#pragma unroll
        for (int j = 0; j < 4; j++)
#pragma unroll
            for (int q = 0; q < 4; q++) acc[i][j][q] = 0.f;

    // issue pair pp: A 32KB contiguous, V two 16KB chunks
    auto issue = [&](int pp) {
        const int s3 = pp % 3;
        {
            const u8* asrc = Abase + (size_t)pp * 32768 + t * 128;
            const u32 ad = sb + (u32)(s3 * 32768 + t * 128);
#pragma unroll
            for (int i = 0; i < 8; i++) CP_ASYNC16(ad + i * 16, asrc + i * 16);
        }
#pragma unroll
        for (int j = 0; j < 2; j++) {
            const u8* vsrc = Vbase + (size_t)(2 * pp + j) * 32768 + t * 64;
            const u32 vd = sb + 98304 + (u32)(s3 * 32768 + j * 16384 + t * 64);
#pragma unroll
            for (int i = 0; i < 4; i++) CP_ASYNC16(vd + i * 16, vsrc + i * 16);
        }
        CP_COMMIT();
    };

    issue(0); issue(1);
    const int lr = lane & 15;

    for (int pp = 0; pp < 16; pp++) {
        if (pp < 15) { CP_WAITG(1); } else { CP_WAITG(0); }
        __syncthreads();
        if (pp + 2 < 16) issue(pp + 2);
#pragma unroll
        for (int sub = 0; sub < 2; sub++) {
            const u32 AB = sb + (u32)((pp % 3) * 32768 + sub * 16384);
            const u32 VB = sb + 98304 + (u32)((pp % 3) * 32768 + sub * 16384);
#pragma unroll
            for (int ks = 0; ks < 4; ks++) {
                const u32 kb = (u32)((ks * 16 + (lane >> 4) * 8) * 2);
                u32 a[4][4], bv[2][4];
#pragma unroll
                for (int mf = 0; mf < 4; mf++) {
                    const int r = wm * 64 + mf * 16 + lr;
                    ldsm4(a[mf], AB + (u32)(r * 128) + (kb ^ ((u32)((r & 7) * 16))));
                }
#pragma unroll
                for (int nb = 0; nb < 2; nb++) {
                    const int r = wn * 32 + nb * 16 + lr;
                    ldsm4(bv[nb], VB + (u32)(r * 128) + (kb ^ ((u32)((r & 7) * 16))));
                }
#pragma unroll
                for (int mf = 0; mf < 4; mf++)
#pragma unroll
                    for (int n8 = 0; n8 < 4; n8++) {
                        const int nb = n8 >> 1, i = n8 & 1;
                        mma_f16(acc[mf][n8], a[mf], bv[nb][i], bv[nb][i + 2]);
                    }
            }
        }
    }

    const int g = lane >> 2, tig = lane & 3;
#pragma unroll
    for (int mf = 0; mf < 4; mf++) {
        const int r0 = wm * 64 + mf * 16 + g;
        const int r1 = r0 + 8;
        const float inv0 = inv[r0], inv1 = inv[r1];
        float* po0 = outp + ((size_t)(b * N_ + mt * 128 + r0)) * VD + ntv * 128;
        float* po1 = outp + ((size_t)(b * N_ + mt * 128 + r1)) * VD + ntv * 128;
#pragma unroll
        for (int n8 = 0; n8 < 4; n8++) {
            const int cc = wn * 32 + n8 * 8 + tig * 2;
            *(float2*)(po0 + cc) = make_float2(acc[mf][n8][0] * inv0, acc[mf][n8][1] * inv0);
            *(float2*)(po1 + cc) = make_float2(acc[mf][n8][2] * inv1, acc[mf][n8][3] * inv1);
        }
    }
}

// ============================================================
extern "C" void kernel_launch(void* const* d_in, const int* in_sizes, int n_in,
                              void* d_out, int out_size) {
    (void)in_sizes; (void)n_in; (void)out_size;
    const float* k1 = (const float*)d_in[0];
    const float* k2 = (const float*)d_in[1];
    const float* v1 = (const float*)d_in[2];
    const float* v2 = (const float*)d_in[3];
    const float* W1 = (const float*)d_in[4];
    const float* b1 = (const float*)d_in[5];
    const float* W2 = (const float*)d_in[6];
    const float* b2 = (const float*)d_in[7];
    float* out = (float*)d_out;
    float* o2_out = out;
    float* o1_out = out + (size_t)B_ * N_ * VD;

    cudaFuncSetAttribute(proj_kernel, cudaFuncAttributeMaxDynamicSharedMemorySize, P_SMEM);
    cudaFuncSetAttribute(score_kernel, cudaFuncAttributeMaxDynamicSharedMemorySize, SC_SMEM);
    cudaFuncSetAttribute(exppack_kernel, cudaFuncAttributeMaxDynamicSharedMemorySize, EF_SMEM);
    cudaFuncSetAttribute(o_kernel, cudaFuncAttributeMaxDynamicSharedMemorySize, O_SMEM);

    proj_kernel<<<dim3(128, 2), 256, P_SMEM>>>(k1, W1, b1, k2, W2, b2);       // 0
    score_kernel<<<dim3(16, 16, B_), 256, SC_SMEM>>>();                        // 1
    maxreduce_kernel<<<dim3((B_ * N_) / 32, 2), 256>>>();                      // 2
    exppack_kernel<<<dim3(16, 16, B_ * 2), 256, EF_SMEM>>>();                  // 3 <- ncu
    vpack_kernel<<<dim3(32, B_, 2), 256>>>(v1, v2);                            // 4
    sumreduce_kernel<<<dim3((B_ * N_) / 32, 2), 256>>>();                      // 5
    o_kernel<<<dim3(32, B_, 2), 256, O_SMEM>>>(o2_out, o1_out);                // 6
}

// round 17
// speedup vs baseline: 1.1654x; 1.1654x over previous
#include <cuda_runtime.h>
#include <cuda_fp16.h>
#include <cstdint>
#include <cstddef>

#define B_  8
#define N_  2048
#define KD  256
#define VD  256
#define AD  128
#define NEG_INF (-3.402823466e38f)

typedef unsigned char u8;
typedef unsigned int  u32;

// ------------------- device scratch -------------------
__device__ __align__(16) u8 g_k1pack[(size_t)B_ * 16 * 2 * 32768];   // 8 MB
__device__ __align__(16) u8 g_k2pack[(size_t)B_ * 16 * 2 * 32768];   // 8 MB
__device__ __align__(16) u8 g_v1pack[(size_t)B_ * 32 * 32768];       // 8 MB
__device__ __align__(16) u8 g_v2pack[(size_t)B_ * 32 * 32768];       // 8 MB
__device__ float g_S[(size_t)B_ * N_ * N_];                          // 128 MB
__device__ __align__(16) u8 g_A2[(size_t)B_ * 16 * 32 * 16384];      // 64 MB
__device__ __align__(16) u8 g_A1[(size_t)B_ * 16 * 32 * 16384];      // 64 MB
__device__ float g_rmpart[(size_t)B_ * N_ * 64];
__device__ float g_cmpart[(size_t)B_ * N_ * 32];
__device__ float g_rspart[(size_t)B_ * N_ * 64];   // exppack writes even pair-slots; odd stay 0
__device__ float g_cspart[(size_t)B_ * N_ * 64];   // exppack writes even pair-slots; odd stay 0
__device__ float g_rowmax[B_ * N_];
__device__ float g_colmax[B_ * N_];

// ------------------- helpers -------------------
__device__ __forceinline__ u32 smem_u32(const void* p) {
    u32 a;
    asm("{ .reg .u64 t; cvta.to.shared.u64 t, %1; cvt.u32.u64 %0, t; }" : "=r"(a) : "l"(p));
    return a;
}
__device__ __forceinline__ u32 f16x2_pack(float a, float b) {
    u32 r;
    asm("cvt.rn.f16x2.f32 %0, %1, %2;" : "=r"(r) : "f"(b), "f"(a));
    return r;
}
__device__ __forceinline__ void split2(float f0, float f1, u32& hi, u32& lo) {
    u32 h;
    asm("cvt.rn.bf16x2.f32 %0, %1, %2;" : "=r"(h) : "f"(f1), "f"(f0));
    float h0 = __uint_as_float(h << 16);
    float h1 = __uint_as_float(h & 0xFFFF0000u);
    u32 l;
    asm("cvt.rn.bf16x2.f32 %0, %1, %2;" : "=r"(l) : "f"(f1 - h1), "f"(f0 - h0));
    hi = h; lo = l;
}
__device__ __forceinline__ void mma_bf16(float* c, const u32* a, u32 b0, u32 b1) {
    asm volatile(
        "mma.sync.aligned.m16n8k16.row.col.f32.bf16.bf16.f32 "
        "{%0,%1,%2,%3}, {%4,%5,%6,%7}, {%8,%9}, {%0,%1,%2,%3};"
        : "+f"(c[0]), "+f"(c[1]), "+f"(c[2]), "+f"(c[3])
        : "r"(a[0]), "r"(a[1]), "r"(a[2]), "r"(a[3]), "r"(b0), "r"(b1));
}
__device__ __forceinline__ void mma_f16(float* c, const u32* a, u32 b0, u32 b1) {
    asm volatile(
        "mma.sync.aligned.m16n8k16.row.col.f32.f16.f16.f32 "
        "{%0,%1,%2,%3}, {%4,%5,%6,%7}, {%8,%9}, {%0,%1,%2,%3};"
        : "+f"(c[0]), "+f"(c[1]), "+f"(c[2]), "+f"(c[3])
        : "r"(a[0]), "r"(a[1]), "r"(a[2]), "r"(a[3]), "r"(b0), "r"(b1));
}
__device__ __forceinline__ void ldsm4(u32* r, u32 addr) {
    asm volatile("ldmatrix.sync.aligned.m8n8.x4.shared.b16 {%0,%1,%2,%3}, [%4];"
                 : "=r"(r[0]), "=r"(r[1]), "=r"(r[2]), "=r"(r[3]) : "r"(addr));
}
#define CP_ASYNC16(dst, src)                                                \
    asm volatile("cp.async.cg.shared.global [%0], [%1], 16;"                \
                 :: "r"(dst), "l"(__cvta_generic_to_global(src)))
#define CP_COMMIT()  asm volatile("cp.async.commit_group;")
#define CP_WAITG(n)  asm volatile("cp.async.wait_group %0;" :: "n"(n))

// ============================================================
// prep = proj + vpack merged (disjoint blockIdx.x ranges; vpack hides under proj)
// x < 128: proj CTA (m0 = x*128, which = y)
// x >= 128: vpack CTA (idx = x-128: kc = idx&31, b = idx>>5, which = y)
// ============================================================
#define P_SMEM 99840
__global__ __launch_bounds__(256) void prep_kernel(const float* __restrict__ k1,
                                                   const float* __restrict__ W1,
                                                   const float* __restrict__ b1v,
                                                   const float* __restrict__ k2,
                                                   const float* __restrict__ W2,
                                                   const float* __restrict__ b2v,
                                                   const float* __restrict__ v1,
                                                   const float* __restrict__ v2) {
    extern __shared__ u8 sm[];
    const int which = blockIdx.y;
    const int t = threadIdx.x;

    if (blockIdx.x >= 128) {
        // ---------------- vpack path ----------------
        float* sv = (float*)sm;   // [64][68]
        const int idx = blockIdx.x - 128;
        const int kc = idx & 31, b = idx >> 5;
        const float* v = which ? v2 : v1;
        u8* dst = which ? g_v2pack : g_v1pack;
        u8* tile = dst + ((size_t)b * 32 + kc) * 32768;
        for (int dc = 0; dc < 4; dc++) {
#pragma unroll
            for (int i = 0; i < 4; i++) {
                const int q = t + i * 256;
                const int kr = q >> 4, dl = (q & 15) * 4;
                float4 f = *(const float4*)(v + ((size_t)b * N_ + kc * 64 + kr) * VD + dc * 64 + dl);
                sv[(dl + 0) * 68 + kr] = f.x; sv[(dl + 1) * 68 + kr] = f.y;
                sv[(dl + 2) * 68 + kr] = f.z; sv[(dl + 3) * 68 + kr] = f.w;
            }
            __syncthreads();
            const int dl = t >> 2, q = t & 3;
            const int row = dc * 64 + dl;
            const u32 xv = (u32)((row & 7) * 16);
#pragma unroll
            for (int j = 0; j < 4; j++) {
                const int k0 = q * 16 + j * 4;
                u32 p01 = f16x2_pack(sv[(k0 + 0) * 68 + 0 * 0 + dl * 0 + 0], 0.f);  // placeholder (never used)
                (void)p01;
                u32 a01 = f16x2_pack(sv[dl * 68 + k0 + 0] * 0.f, 0.f);              // placeholder
                (void)a01;
                // correct packing: sv is [d][k] -> sv[dl][k]
                u32 q01 = f16x2_pack(sv[dl * 68 + k0 + 0], sv[dl * 68 + k0 + 1]);
                u32 q23 = f16x2_pack(sv[dl * 68 + k0 + 2], sv[dl * 68 + k0 + 3]);
                *(uint2*)(tile + row * 128 + (((u32)(k0 * 2)) ^ xv)) = make_uint2(q01, q23);
            }
            __syncthreads();
        }
        return;
    }

    // ---------------- proj path (unchanged body) ----------------
    const u32 sb = smem_u32(sm);
    float* Wst = (float*)(sm + 65536);
    float* bc  = (float*)(sm + 99328);
    const float* A = which ? k2 : k1;
    const float* W = which ? W2 : W1;
    const float* bias = which ? b2v : b1v;
    const int lane = t & 31, wid = t >> 5;
    const int wm = wid & 1, wn = wid >> 1;
    const int m0 = blockIdx.x * 128;
    if (t < 128) bc[t] = bias[t];

    float acc[4][4][4];
#pragma unroll
    for (int i = 0; i < 4; i++)
#pragma unroll
        for (int j = 0; j < 4; j++)
#pragma unroll
            for (int q = 0; q < 4; q++) acc[i][j][q] = 0.f;

    const int lr = lane & 15;
    for (int kc = 0; kc < 4; kc++) {
        __syncthreads();
        {
            const int m = t >> 1, kh = (t & 1) * 32;
            const float* Ar = A + (size_t)(m0 + m) * KD + kc * 64 + kh;
            const u32 xv = (u32)((m & 7) * 16);
#pragma unroll
            for (int j = 0; j < 8; j++) {
                float4 f = *(const float4*)(Ar + 4 * j);
                u32 h01, l01, h23, l23;
                split2(f.x, f.y, h01, l01); split2(f.z, f.w, h23, l23);
                const u32 off = (u32)(m * 128) + (((u32)((kh + 4 * j) * 2)) ^ xv);
                *(uint2*)(sm + off)         = make_uint2(h01, h23);
                *(uint2*)(sm + 16384 + off) = make_uint2(l01, l23);
            }
        }
        {
            const int k = t >> 2, ns = (t & 3) * 32;
            const float* Wr = W + (size_t)(kc * 64 + k) * AD + ns;
#pragma unroll
            for (int j = 0; j < 8; j++)
                *(float4*)&Wst[k * 132 + ns + 4 * j] = *(const float4*)(Wr + 4 * j);
        }
        __syncthreads();
        {
            const int n = t >> 1, kh = (t & 1) * 32;
            const u32 xv = (u32)((n & 7) * 16);
#pragma unroll
            for (int jq = 0; jq < 8; jq++) {
                float w0 = Wst[(kh + 4 * jq + 0) * 132 + n];
                float w1 = Wst[(kh + 4 * jq + 1) * 132 + n];
                float w2 = Wst[(kh + 4 * jq + 2) * 132 + n];
                float w3 = Wst[(kh + 4 * jq + 3) * 132 + n];
                u32 h01, l01, h23, l23;
                split2(w0, w1, h01, l01); split2(w2, w3, h23, l23);
                const u32 off = (u32)(n * 128) + (((u32)((kh + 4 * jq) * 2)) ^ xv);
                *(uint2*)(sm + 32768 + off) = make_uint2(h01, h23);
                *(uint2*)(sm + 49152 + off) = make_uint2(l01, l23);
            }
        }
        __syncthreads();
#pragma unroll
        for (int ks = 0; ks < 4; ks++) {
            const u32 kb = (u32)((ks * 16 + (lane >> 4) * 8) * 2);
            u32 ah[4][4], al[4][4], bh[2][4], bl[2][4];
#pragma unroll
            for (int mf = 0; mf < 4; mf++) {
                const int r = wm * 64 + mf * 16 + lr;
                const u32 ro = (u32)(r * 128) + (kb ^ ((u32)((r & 7) * 16)));
                ldsm4(ah[mf], sb + ro);
                ldsm4(al[mf], sb + 16384 + ro);
            }
#pragma unroll
            for (int nb = 0; nb < 2; nb++) {
                const int r = wn * 32 + nb * 16 + lr;
                const u32 ro = (u32)(r * 128) + (kb ^ ((u32)((r & 7) * 16)));
                ldsm4(bh[nb], sb + 32768 + ro);
                ldsm4(bl[nb], sb + 49152 + ro);
            }
#pragma unroll
            for (int mf = 0; mf < 4; mf++)
#pragma unroll
                for (int n8 = 0; n8 < 4; n8++) {
                    const int nb = n8 >> 1, i = n8 & 1;
                    mma_bf16(acc[mf][n8], ah[mf], bh[nb][i], bh[nb][i + 2]);
                    mma_bf16(acc[mf][n8], al[mf], bh[nb][i], bh[nb][i + 2]);
                    mma_bf16(acc[mf][n8], ah[mf], bl[nb][i], bl[nb][i + 2]);
                }
        }
    }
    __syncthreads();
    float* smT = (float*)sm;
    const int g = lane >> 2, tig = lane & 3;
#pragma unroll
    for (int mf = 0; mf < 4; mf++)
#pragma unroll
        for (int n8 = 0; n8 < 4; n8++) {
            const int r = wm * 64 + mf * 16 + g;
            const int c = wn * 32 + n8 * 8 + tig * 2;
            const float b0 = bc[c], b1 = bc[c + 1];
            *(float2*)&smT[r * 132 + c]       = make_float2(acc[mf][n8][0] + b0, acc[mf][n8][1] + b1);
            *(float2*)&smT[(r + 8) * 132 + c] = make_float2(acc[mf][n8][2] + b0, acc[mf][n8][3] + b1);
        }
    __syncthreads();
    {
        const int b_ = m0 / N_, mt = (m0 % N_) / 128;
        u8* hibase = (which ? g_k2pack : g_k1pack) + ((size_t)(b_ * 16 + mt) * 2) * 32768;
        u8* lobase = hibase + 32768;
        const int row = t >> 1, ch = t & 1;
        const u32 xv = (u32)((row & 7) * 16);
#pragma unroll
        for (int j = 0; j < 16; j++) {
            float f0 = smT[row * 132 + ch * 64 + 4 * j + 0];
            float f1 = smT[row * 132 + ch * 64 + 4 * j + 1];
            float f2 = smT[row * 132 + ch * 64 + 4 * j + 2];
            float f3 = smT[row * 132 + ch * 64 + 4 * j + 3];
            u32 h01, l01, h23, l23;
            split2(f0, f1, h01, l01); split2(f2, f3, h23, l23);
            const u32 off = (u32)(ch * 16384 + row * 128) + (((u32)(8 * j)) ^ xv);
            *(uint2*)(hibase + off) = make_uint2(h01, h23);
            *(uint2*)(lobase + off) = make_uint2(l01, l23);
        }
    }
}

// ============================================================
// score (unchanged)
// ============================================================
#define SC_SMEM 65536
__global__ __launch_bounds__(256) void score_kernel() {
    extern __shared__ u8 sm[];
    const u32 sb = smem_u32(sm);
    const int t = threadIdx.x, lane = t & 31, wid = t >> 5;
    const int wm = wid & 1, wn = wid >> 1;
    const int b = blockIdx.z, mt = blockIdx.y, nt = blockIdx.x;

    const u8* a_hi = g_k1pack + ((size_t)(b * 16 + mt) * 2) * 32768;
    const u8* a_lo = a_hi + 32768;
    const u8* b_hi = g_k2pack + ((size_t)(b * 16 + nt) * 2) * 32768;
    const u8* b_lo = b_hi + 32768;

    float acc[4][4][4];
#pragma unroll
    for (int i = 0; i < 4; i++)
#pragma unroll
        for (int j = 0; j < 4; j++)
#pragma unroll
            for (int q = 0; q < 4; q++) acc[i][j][q] = 0.f;

    const int lr = lane & 15;
    for (int kc = 0; kc < 2; kc++) {
        __syncthreads();
        const u32 off0 = (u32)(kc * 16384);
#pragma unroll
        for (int j = 0; j < 4; j++) {
            const u32 o = (u32)((j * 256 + t) * 16);
            CP_ASYNC16(sb + o,         a_hi + off0 + o);
            CP_ASYNC16(sb + 16384 + o, a_lo + off0 + o);
            CP_ASYNC16(sb + 32768 + o, b_hi + off0 + o);
            CP_ASYNC16(sb + 49152 + o, b_lo + off0 + o);
        }
        CP_COMMIT(); CP_WAITG(0);
        __syncthreads();
#pragma unroll
        for (int ks = 0; ks < 4; ks++) {
            const u32 kb = (u32)((ks * 16 + (lane >> 4) * 8) * 2);
            u32 ah[4][4], al[4][4], bh[2][4], bl[2][4];
#pragma unroll
            for (int mf = 0; mf < 4; mf++) {
                const int r = wm * 64 + mf * 16 + lr;
                const u32 ro = (u32)(r * 128) + (kb ^ ((u32)((r & 7) * 16)));
                ldsm4(ah[mf], sb + ro);
                ldsm4(al[mf], sb + 16384 + ro);
            }
#pragma unroll
            for (int nb = 0; nb < 2; nb++) {
                const int r = wn * 32 + nb * 16 + lr;
                const u32 ro = (u32)(r * 128) + (kb ^ ((u32)((r & 7) * 16)));
                ldsm4(bh[nb], sb + 32768 + ro);
                ldsm4(bl[nb], sb + 49152 + ro);
            }
#pragma unroll
            for (int mf = 0; mf < 4; mf++)
#pragma unroll
                for (int n8 = 0; n8 < 4; n8++) {
                    const int nb = n8 >> 1, i = n8 & 1;
                    mma_bf16(acc[mf][n8], ah[mf], bh[nb][i], bh[nb][i + 2]);
                    mma_bf16(acc[mf][n8], al[mf], bh[nb][i], bh[nb][i + 2]);
                    mma_bf16(acc[mf][n8], ah[mf], bl[nb][i], bl[nb][i + 2]);
                }
        }
    }

    const int g = lane >> 2, tig = lane & 3;
    float rowm[8], colm[8];
#pragma unroll
    for (int i = 0; i < 8; i++) { rowm[i] = NEG_INF; colm[i] = NEG_INF; }
    float* Sp = g_S + ((size_t)(b * N_ + mt * 128)) * N_ + nt * 128;
#pragma unroll
    for (int mf = 0; mf < 4; mf++) {
        const int r0 = wm * 64 + mf * 16 + g;
#pragma unroll
        for (int n8 = 0; n8 < 4; n8++) {
            const int c = wn * 32 + n8 * 8 + tig * 2;
            const float v0 = acc[mf][n8][0], v1 = acc[mf][n8][1];
            const float v2 = acc[mf][n8][2], v3 = acc[mf][n8][3];
            *(float2*)(Sp + (size_t)r0 * N_ + c)       = make_float2(v0, v1);
            *(float2*)(Sp + (size_t)(r0 + 8) * N_ + c) = make_float2(v2, v3);
            rowm[mf * 2 + 0] = fmaxf(rowm[mf * 2 + 0], fmaxf(v0, v1));
            rowm[mf * 2 + 1] = fmaxf(rowm[mf * 2 + 1], fmaxf(v2, v3));
            colm[n8 * 2 + 0] = fmaxf(colm[n8 * 2 + 0], fmaxf(v0, v2));
            colm[n8 * 2 + 1] = fmaxf(colm[n8 * 2 + 1], fmaxf(v1, v3));
        }
    }
#pragma unroll
    for (int i = 0; i < 8; i++) {
        rowm[i] = fmaxf(rowm[i], __shfl_xor_sync(0xffffffffu, rowm[i], 1));
        rowm[i] = fmaxf(rowm[i], __shfl_xor_sync(0xffffffffu, rowm[i], 2));
        colm[i] = fmaxf(colm[i], __shfl_xor_sync(0xffffffffu, colm[i], 4));
        colm[i] = fmaxf(colm[i], __shfl_xor_sync(0xffffffffu, colm[i], 8));
        colm[i] = fmaxf(colm[i], __shfl_xor_sync(0xffffffffu, colm[i], 16));
    }
    if (tig == 0) {
#pragma unroll
        for (int mf = 0; mf < 4; mf++)
#pragma unroll
            for (int rh = 0; rh < 2; rh++) {
                const int row = mt * 128 + wm * 64 + mf * 16 + rh * 8 + g;
                g_rmpart[((size_t)(b * N_ + row)) * 64 + nt * 4 + wn] = rowm[mf * 2 + rh];
            }
    }
    if (g == 0) {
#pragma unroll
        for (int n8 = 0; n8 < 4; n8++)
#pragma unroll
            for (int cp = 0; cp < 2; cp++) {
                const int col = nt * 128 + wn * 32 + n8 * 8 + tig * 2 + cp;
                g_cmpart[((size_t)(b * N_ + col)) * 32 + mt * 2 + wm] = colm[n8 * 2 + cp];
            }
    }
}

// ============================================================
// maxreduce (unchanged)
// ============================================================
__global__ void maxreduce_kernel() {
    const int which = blockIdx.y;
    const int t = threadIdx.x;
    const int item = blockIdx.x * 32 + (t >> 3);
    const int j = t & 7;
    float m;
    if (which == 0) {
        const float* p = g_rmpart + (size_t)item * 64 + j * 8;
        float4 a = *(const float4*)p, b4 = *(const float4*)(p + 4);
        m = fmaxf(fmaxf(fmaxf(a.x, a.y), fmaxf(a.z, a.w)),
                  fmaxf(fmaxf(b4.x, b4.y), fmaxf(b4.z, b4.w)));
    } else {
        const float* p = g_cmpart + (size_t)item * 32 + j * 4;
        float4 a = *(const float4*)p;
        m = fmaxf(fmaxf(a.x, a.y), fmaxf(a.z, a.w));
    }
    m = fmaxf(m, __shfl_xor_sync(0xffffffffu, m, 1));
    m = fmaxf(m, __shfl_xor_sync(0xffffffffu, m, 2));
    m = fmaxf(m, __shfl_xor_sync(0xffffffffu, m, 4));
    if (j == 0) (which ? g_colmax : g_rowmax)[item] = m;
}

// ============================================================
// exppack FUSED v2 (unchanged R15)
// ============================================================
#define EF_SMEM 20608
__global__ __launch_bounds__(256) void exppack_kernel() {
    extern __shared__ u8 sm[];
    const int t = threadIdx.x;
    const int nt = blockIdx.x, mt = blockIdx.y;
    const int b = blockIdx.z >> 1, half = blockIdx.z & 1;

    // Phase A: register-direct
    {
        const int ch = t & 7, rg = t >> 3;
        u8* tile = g_A2 + (((size_t)(b * 16 + mt) * 32) + nt * 2 + half) * 16384;
#pragma unroll
        for (int i = 0; i < 4; i++) {
            const int r = rg + i * 32;
            const float* Sp = g_S + ((size_t)(b * N_ + mt * 128 + r)) * N_
                              + nt * 128 + half * 64 + ch * 8;
            const float rm = g_rowmax[b * N_ + mt * 128 + r];
            float4 f0 = *(const float4*)Sp;
            float4 f1 = *(const float4*)(Sp + 4);
            float e0 = __expf(f0.x - rm), e1 = __expf(f0.y - rm);
            float e2 = __expf(f0.z - rm), e3 = __expf(f0.w - rm);
            float e4 = __expf(f1.x - rm), e5 = __expf(f1.y - rm);
            float e6 = __expf(f1.z - rm), e7 = __expf(f1.w - rm);
            float rs = ((e0 + e1) + (e2 + e3)) + ((e4 + e5) + (e6 + e7));
            uint4 v = make_uint4(f16x2_pack(e0, e1), f16x2_pack(e2, e3),
                                 f16x2_pack(e4, e5), f16x2_pack(e6, e7));
            const u32 off = (u32)(r * 128) + (((u32)(ch * 16)) ^ ((u32)((r & 7) * 16)));
            *(uint4*)(tile + off) = v;
            rs += __shfl_xor_sync(0xffffffffu, rs, 1);
            rs += __shfl_xor_sync(0xffffffffu, rs, 2);
            rs += __shfl_xor_sync(0xffffffffu, rs, 4);
            if (ch == 0)
                g_rspart[((size_t)(b * N_ + mt * 128 + r)) * 64 + nt * 4 + half * 2] = rs;
        }
    }

    // Phase T: staged
    {
        float* csbuf = (float*)(sm + 16384);
        const int lane5 = t & 31, kseg = t >> 5;
        const int colq = lane5 * 4;
        const int k0 = mt * 128 + half * 64 + kseg * 8;
        const float* Sp = g_S + ((size_t)(b * N_) + k0) * N_ + nt * 128 + colq;
        const float4 cm4 = *(const float4*)(g_colmax + b * N_ + nt * 128 + colq);

        float e[8][4];
        float cs[4] = {0.f, 0.f, 0.f, 0.f};
#pragma unroll
        for (int k = 0; k < 8; k++) {
            float4 f = *(const float4*)(Sp + (size_t)k * N_);
            e[k][0] = __expf(f.x - cm4.x); e[k][1] = __expf(f.y - cm4.y);
            e[k][2] = __expf(f.z - cm4.z); e[k][3] = __expf(f.w - cm4.w);
            cs[0] += e[k][0]; cs[1] += e[k][1]; cs[2] += e[k][2]; cs[3] += e[k][3];
        }
#pragma unroll
        for (int j = 0; j < 4; j++) {
            const int c = (j + (lane5 >> 1)) & 3;
            const int row = colq + c;
            uint4 v = make_uint4(f16x2_pack(e[0][c], e[1][c]), f16x2_pack(e[2][c], e[3][c]),
                                 f16x2_pack(e[4][c], e[5][c]), f16x2_pack(e[6][c], e[7][c]));
            const u32 off = (u32)(row * 128) + (((u32)(kseg * 16)) ^ ((u32)((row & 7) * 16)));
            *(uint4*)(sm + off) = v;
        }
#pragma unroll
        for (int c = 0; c < 4; c++) csbuf[kseg * 132 + colq + c] = cs[c];
        __syncthreads();
        if (t < 128) {
            float s = 0.f;
#pragma unroll
            for (int ks2 = 0; ks2 < 8; ks2++) s += csbuf[ks2 * 132 + t];
            g_cspart[((size_t)(b * N_ + nt * 128 + t)) * 64 + mt * 4 + half * 2] = s;
        }
        u8* dst = g_A1 + (((size_t)(b * 16 + nt) * 32) + mt * 2 + half) * 16384;
#pragma unroll
        for (int i = 0; i < 4; i++) {
            const int q = (t & 7) + ((t >> 3) + i * 32) * 8;
            *(uint4*)(dst + q * 16) = *(const uint4*)(sm + q * 16);
        }
    }
}

// ============================================================
// o (R12 version + inline inv reduction; sumreduce kernel eliminated)
// smem: A 3x16K @0 | V 3x16K @49152 | red[128] @98304
// ============================================================
#define O_SMEM 98816
__global__ __launch_bounds__(256, 2) void o_kernel(float* __restrict__ o2_out,
                                                   float* __restrict__ o1_out) {
    extern __shared__ u8 sm[];
    const u32 sb = smem_u32(sm);
    const int t = threadIdx.x, lane = t & 31, wid = t >> 5;
    const int wm = wid & 1, wn = wid >> 1;
    const int which = blockIdx.z, b = blockIdx.y;
    const int mt = blockIdx.x >> 1, ntv = blockIdx.x & 1;
    float* red = (float*)(sm + 98304);

    const u8* Abase = (which ? g_A1 : g_A2) + ((size_t)(b * 16 + mt) * 32) * 16384;
    const u8* Vbase = (which ? g_v1pack : g_v2pack) + ((size_t)b * 32) * 32768 + (size_t)ntv * 16384;
    float* outp = which ? o1_out : o2_out;

    float acc[4][4][4];
#pragma unroll
    for (int i = 0; i < 4; i++)
#pragma unroll
        for (int j = 0; j < 4; j++)
#pragma unroll
            for (int q = 0; q < 4; q++) acc[i][j][q] = 0.f;

    auto issue = [&](int cc) {
        const int s3 = cc % 3;
        const u8* asrc = Abase + (size_t)cc * 16384 + t * 64;
        const u8* vsrc = Vbase + (size_t)cc * 32768 + t * 64;
        const u32 ad = sb + (u32)(s3 * 16384 + t * 64);
        const u32 vd = sb + 49152 + (u32)(s3 * 16384 + t * 64);
#pragma unroll
        for (int i = 0; i < 4; i++) CP_ASYNC16(ad + i * 16, asrc + i * 16);
#pragma unroll
        for (int i = 0; i < 4; i++) CP_ASYNC16(vd + i * 16, vsrc + i * 16);
        CP_COMMIT();
    };

    issue(0); issue(1);

    // inline inv reduction (overlaps prologue cp.async)
    {
        const int row = t >> 1, h = t & 1;
        const float* p = (which ? g_cspart : g_rspart)
                         + ((size_t)(b * N_ + mt * 128 + row)) * 64 + h * 32;
        float s = 0.f;
#pragma unroll
        for (int j = 0; j < 8; j++) {
            float4 a = *(const float4*)(p + 4 * j);
            s += (a.x + a.y) + (a.z + a.w);
        }
        s += __shfl_xor_sync(0xffffffffu, s, 1);
        if (h == 0) red[row] = 1.f / s;
    }

    const int lr = lane & 15;

    for (int c = 0; c < 32; c++) {
        if (c < 31) { CP_WAITG(1); } else { CP_WAITG(0); }
        __syncthreads();
        if (c + 2 < 32) issue(c + 2);
        const u32 AB = sb + (u32)((c % 3) * 16384);
        const u32 VB = sb + 49152 + (u32)((c % 3) * 16384);
#pragma unroll
        for (int ks = 0; ks < 4; ks++) {
            const u32 kb = (u32)((ks * 16 + (lane >> 4) * 8) * 2);
            u32 a[4][4], bv[2][4];
#pragma unroll
            for (int mf = 0; mf < 4; mf++) {
                const int r = wm * 64 + mf * 16 + lr;
                ldsm4(a[mf], AB + (u32)(r * 128) + (kb ^ ((u32)((r & 7) * 16))));
            }
#pragma unroll
            for (int nb = 0; nb < 2; nb++) {
                const int r = wn * 32 + nb * 16 + lr;
                ldsm4(bv[nb], VB + (u32)(r * 128) + (kb ^ ((u32)((r & 7) * 16))));
            }
#pragma unroll
            for (int mf = 0; mf < 4; mf++)
#pragma unroll
                for (int n8 = 0; n8 < 4; n8++) {
                    const int nb = n8 >> 1, i = n8 & 1;
                    mma_f16(acc[mf][n8], a[mf], bv[nb][i], bv[nb][i + 2]);
                }
        }
    }

    const int g = lane >> 2, tig = lane & 3;
#pragma unroll
    for (int mf = 0; mf < 4; mf++) {
        const int r0 = wm * 64 + mf * 16 + g;
        const int r1 = r0 + 8;
        const float inv0 = red[r0], inv1 = red[r1];
        float* po0 = outp + ((size_t)(b * N_ + mt * 128 + r0)) * VD + ntv * 128;
        float* po1 = outp + ((size_t)(b * N_ + mt * 128 + r1)) * VD + ntv * 128;
#pragma unroll
        for (int n8 = 0; n8 < 4; n8++) {
            const int cc = wn * 32 + n8 * 8 + tig * 2;
            *(float2*)(po0 + cc) = make_float2(acc[mf][n8][0] * inv0, acc[mf][n8][1] * inv0);
            *(float2*)(po1 + cc) = make_float2(acc[mf][n8][2] * inv1, acc[mf][n8][3] * inv1);
        }
    }
}

// ============================================================
extern "C" void kernel_launch(void* const* d_in, const int* in_sizes, int n_in,
                              void* d_out, int out_size) {
    (void)in_sizes; (void)n_in; (void)out_size;
    const float* k1 = (const float*)d_in[0];
    const float* k2 = (const float*)d_in[1];
    const float* v1 = (const float*)d_in[2];
    const float* v2 = (const float*)d_in[3];
    const float* W1 = (const float*)d_in[4];
    const float* b1 = (const float*)d_in[5];
    const float* W2 = (const float*)d_in[6];
    const float* b2 = (const float*)d_in[7];
    float* out = (float*)d_out;
    float* o2_out = out;
    float* o1_out = out + (size_t)B_ * N_ * VD;

    cudaFuncSetAttribute(prep_kernel, cudaFuncAttributeMaxDynamicSharedMemorySize, P_SMEM);
    cudaFuncSetAttribute(score_kernel, cudaFuncAttributeMaxDynamicSharedMemorySize, SC_SMEM);
    cudaFuncSetAttribute(exppack_kernel, cudaFuncAttributeMaxDynamicSharedMemorySize, EF_SMEM);
    cudaFuncSetAttribute(o_kernel, cudaFuncAttributeMaxDynamicSharedMemorySize, O_SMEM);

    prep_kernel<<<dim3(128 + 32 * B_, 2), 256, P_SMEM>>>(k1, W1, b1, k2, W2, b2, v1, v2);  // 0
    score_kernel<<<dim3(16, 16, B_), 256, SC_SMEM>>>();                                     // 1
    maxreduce_kernel<<<dim3((B_ * N_) / 32, 2), 256>>>();                                   // 2
    exppack_kernel<<<dim3(16, 16, B_ * 2), 256, EF_SMEM>>>();                               // 3 <- ncu
    o_kernel<<<dim3(32, B_, 2), 256, O_SMEM>>>(o2_out, o1_out);                             // 4
}